// round 8
// baseline (speedup 1.0000x reference)
#include <cuda_runtime.h>
#include <cuda_fp16.h>
#include <cstdint>

// ============================================================================
// LSTMCell: gates = [x|h] @ [Wx|Wh]^T + b, then elementwise LSTM math.
// M=16384, N=2048 (4 gates x 512), K=1024.  fp16 tcgen05 GEMM, fp32 accum.
//
// Live path: tcgen05 (sm_103a gencode pass), 2 CTAs/SM, cluster (2,2):
//   - x-pairs (adjacent nblk) share the A tile  -> A bulk-multicast
//   - y-pairs (adjacent m-tile) share the W tile -> W bulk-multicast
//   halves L2->SMEM operand traffic (the measured bottleneck).
// HMMA fallback retained for non-'a' builds.
// ============================================================================

#define DINL __device__ __forceinline__

#if defined(__CUDA_ARCH__)
# if defined(__CUDA_ARCH_FEAT_SM103_ALL) || defined(__CUDA_ARCH_FEAT_SM100_ALL)
#  define TC_OK 1
# else
#  define TC_OK 0
# endif
#else
# define TC_OK 0
#endif

constexpr int B_SZ   = 16384;
constexpr int HIDN   = 512;
constexpr int KDIM   = 1024;
constexpr int TILE_M = 128;
constexpr int MMA_N  = 256;          // 4 gates * 64 hidden cols
constexpr int K_CHUNK = 64;          // fp16 elems per chunk (128 bytes)
constexpr int N_CHUNKS = KDIM / K_CHUNK;  // 16
constexpr int A_BYTES = TILE_M * 128;     // 16384
constexpr int B_BYTES = MMA_N * 128;      // 32768
constexpr int STAGE_BYTES = A_BYTES + B_BYTES; // 49152

constexpr int SMEM_HDR = 2048;

// tcgen05 path: 2 stages -> 2 CTAs/SM
constexpr int TCS = 2;
constexpr int SMEM_TOTAL_TC = SMEM_HDR + TCS * STAGE_BYTES;        // 100352

// HMMA fallback: 4 stages
constexpr int FBS = 4;
constexpr int SMEM_TOTAL_FB = SMEM_HDR + FBS * STAGE_BYTES;        // 198656

// Pre-packed operands (device globals; no runtime allocation).
__device__ __align__(1024) __half g_A[B_SZ / TILE_M][N_CHUNKS][TILE_M * K_CHUNK];
__device__ __align__(1024) __half g_W[8][N_CHUNKS][MMA_N * K_CHUNK];
__device__ float g_bias[4 * HIDN];

DINL uint32_t smem_u32(const void* p) {
    uint32_t a;
    asm("{ .reg .u64 t; cvta.to.shared.u64 t, %1; cvt.u32.u64 %0, t; }" : "=r"(a) : "l"(p));
    return a;
}
DINL void mbar_init(uint32_t a, uint32_t cnt) {
    asm volatile("mbarrier.init.shared.b64 [%0], %1;" :: "r"(a), "r"(cnt) : "memory");
}
DINL void mbar_expect_tx(uint32_t a, uint32_t bytes) {
    asm volatile("mbarrier.arrive.expect_tx.shared.b64 _, [%0], %1;" :: "r"(a), "r"(bytes) : "memory");
}
DINL void mbar_arrive(uint32_t a) {
    asm volatile("mbarrier.arrive.shared.b64 _, [%0];" :: "r"(a) : "memory");
}
DINL void mbar_wait(uint32_t a, uint32_t parity) {
    asm volatile(
        "{\n\t.reg .pred P;\n\t"
        "W_%=:\n\t"
        "mbarrier.try_wait.parity.acquire.cta.shared::cta.b64 P, [%0], %1, 0x989680;\n\t"
        "@P bra.uni D_%=;\n\t"
        "bra.uni W_%=;\n\t"
        "D_%=:\n\t}"
        :: "r"(a), "r"(parity) : "memory");
}
DINL void bulk_g2s(uint32_t dst, const void* src, uint32_t bytes, uint32_t mbar) {
    asm volatile(
        "cp.async.bulk.shared::cta.global.mbarrier::complete_tx::bytes [%0], [%1], %2, [%3];"
        :: "r"(dst), "l"(src), "r"(bytes), "r"(mbar) : "memory");
}

DINL uint32_t sw128(uint32_t off) { return off ^ ((off >> 3) & 0x70); }
DINL float tanh_ap(float x) {
    float y;
    asm("tanh.approx.f32 %0, %1;" : "=f"(y) : "f"(x));
    return y;
}
DINL float fast_sigmoid(float x) { return __fmaf_rn(tanh_ap(0.5f * x), 0.5f, 0.5f); }

// ============================================================================
// Prep kernels (arch-independent, float4 vectorized)
// ============================================================================

__global__ void pack_A(const float* __restrict__ x, const float* __restrict__ h) {
    int idx = blockIdx.x * blockDim.x + threadIdx.x;
    int e = idx * 4;
    if (e >= B_SZ * KDIM) return;
    int m = e >> 10, k = e & 1023;
    const float* src = (k < 512) ? (x + m * 512 + k) : (h + m * 512 + (k - 512));
    float4 v = *reinterpret_cast<const float4*>(src);
    __half2 h0 = __floats2half2_rn(v.x, v.y);
    __half2 h1 = __floats2half2_rn(v.z, v.w);
    uint2 hv;
    hv.x = *reinterpret_cast<uint32_t*>(&h0);
    hv.y = *reinterpret_cast<uint32_t*>(&h1);
    int mt = m >> 7, r = m & 127, kc = k >> 6, cc = k & 63;
    uint32_t off = sw128((uint32_t)(r * 128 + cc * 2));
    *reinterpret_cast<uint2*>(reinterpret_cast<char*>(&g_A[mt][kc][0]) + off) = hv;
}

__global__ void pack_W(const float* __restrict__ Wx0, const float* __restrict__ Wx1,
                       const float* __restrict__ Wx2, const float* __restrict__ Wx3,
                       const float* __restrict__ Wh0, const float* __restrict__ Wh1,
                       const float* __restrict__ Wh2, const float* __restrict__ Wh3) {
    int idx = blockIdx.x * blockDim.x + threadIdx.x;
    int e = idx * 4;
    if (e >= 4 * HIDN * KDIM) return;
    int g = e >> 19;
    int rem = e & ((1 << 19) - 1);
    int j = rem >> 10, k = rem & 1023;
    const float* Wx = (g == 0) ? Wx0 : (g == 1) ? Wx1 : (g == 2) ? Wx2 : Wx3;
    const float* Wh = (g == 0) ? Wh0 : (g == 1) ? Wh1 : (g == 2) ? Wh2 : Wh3;
    const float* src = (k < 512) ? (Wx + j * 512 + k) : (Wh + j * 512 + (k - 512));
    float4 v = *reinterpret_cast<const float4*>(src);
    __half2 h0 = __floats2half2_rn(v.x, v.y);
    __half2 h1 = __floats2half2_rn(v.z, v.w);
    uint2 hv;
    hv.x = *reinterpret_cast<uint32_t*>(&h0);
    hv.y = *reinterpret_cast<uint32_t*>(&h1);
    int nblk = j >> 6;
    int row = g * 64 + (j & 63);
    int kc = k >> 6, cc = k & 63;
    uint32_t off = sw128((uint32_t)(row * 128 + cc * 2));
    *reinterpret_cast<uint2*>(reinterpret_cast<char*>(&g_W[nblk][kc][0]) + off) = hv;
}

__global__ void pack_bias(const float* __restrict__ bx0, const float* __restrict__ bx1,
                          const float* __restrict__ bx2, const float* __restrict__ bx3,
                          const float* __restrict__ bh0, const float* __restrict__ bh1,
                          const float* __restrict__ bh2, const float* __restrict__ bh3) {
    int t = blockIdx.x * blockDim.x + threadIdx.x;
    if (t >= 4 * HIDN) return;
    int g = t >> 9, j = t & 511;
    const float* bx = (g == 0) ? bx0 : (g == 1) ? bx1 : (g == 2) ? bx2 : bx3;
    const float* bh = (g == 0) ? bh0 : (g == 1) ? bh1 : (g == 2) ? bh2 : bh3;
    g_bias[t] = bx[j] + bh[j];
}

// ============================================================================
// tcgen05 path (compiles only on sm_103a/sm_100a PTX targets)
// ============================================================================
#if TC_OK

constexpr uint32_t MMA_IDESC = (8u << 24) | ((MMA_N / 8) << 17) | (1u << 4);
constexpr uint64_t SMEM_DESC_BASE_SW128 =
    (uint64_t(2) << 61) | (uint64_t(1) << 46) | (uint64_t(64) << 32) | (uint64_t(1) << 16);

DINL uint64_t make_desc(uint32_t smem_addr) {
    return SMEM_DESC_BASE_SW128 | ((uint64_t)(smem_addr >> 4) & 0x3FFF);
}
DINL void mma_f16_ss(uint32_t d, uint64_t a, uint64_t b, uint32_t idesc, uint32_t en) {
    asm volatile(
        "{\n\t.reg .pred p;\n\t"
        "setp.ne.u32 p, %4, 0;\n\t"
        "tcgen05.mma.cta_group::1.kind::f16 [%0], %1, %2, %3, {%5, %5, %5, %5}, p;\n\t}"
        :: "r"(d), "l"(a), "l"(b), "r"(idesc), "r"(en), "r"(0u) : "memory");
}
// Bulk copy with cluster multicast: delivers data + complete_tx to the same
// SMEM offset / same-offset mbarrier in every CTA whose bit is set in mask.
DINL void bulk_g2s_mc(uint32_t dst, const void* src, uint32_t bytes, uint32_t mbar,
                      uint16_t mask) {
    asm volatile(
        "cp.async.bulk.shared::cluster.global.mbarrier::complete_tx::bytes.multicast::cluster "
        "[%0], [%1], %2, [%3], %4;"
        :: "r"(dst), "l"(src), "r"(bytes), "r"(mbar), "h"(mask) : "memory");
}
#define TC_ALLOC(sm, n)   asm volatile("tcgen05.alloc.cta_group::1.sync.aligned.shared::cta.b32 [%0], %1;" :: "r"(sm), "r"(n) : "memory")
#define TC_DEALLOC(t, n)  asm volatile("tcgen05.dealloc.cta_group::1.sync.aligned.b32 %0, %1;" :: "r"(t), "r"(n))
#define TC_RELINQ()       asm volatile("tcgen05.relinquish_alloc_permit.cta_group::1.sync.aligned;")
#define TC_COMMIT(mb)     asm volatile("tcgen05.commit.cta_group::1.mbarrier::arrive::one.shared::cluster.b64 [%0];" :: "r"(mb) : "memory")
#define TC_COMMIT_MC(mb, mask) \
    asm volatile("tcgen05.commit.cta_group::1.mbarrier::arrive::one.shared::cluster.multicast::cluster.b64 [%0], %1;" \
                 :: "r"(mb), "h"((uint16_t)(mask)) : "memory")
#define TC_FENCE_AFTER()  asm volatile("tcgen05.fence::after_thread_sync;" ::: "memory")
#define TC_WAIT_LD()      asm volatile("tcgen05.wait::ld.sync.aligned;" ::: "memory")
#define CLUSTER_SYNC()    do { \
    asm volatile("barrier.cluster.arrive.aligned;" ::: "memory"); \
    asm volatile("barrier.cluster.wait.aligned;" ::: "memory"); } while (0)

#define TC_LD_X16(r, addr) \
    asm volatile( \
        "tcgen05.ld.sync.aligned.32x32b.x16.b32 " \
        "{%0, %1, %2, %3, %4, %5, %6, %7, %8, %9, %10, %11, %12, %13, %14, %15}, [%16];" \
        : "=r"((r)[0]), "=r"((r)[1]), "=r"((r)[2]), "=r"((r)[3]), \
          "=r"((r)[4]), "=r"((r)[5]), "=r"((r)[6]), "=r"((r)[7]), \
          "=r"((r)[8]), "=r"((r)[9]), "=r"((r)[10]), "=r"((r)[11]), \
          "=r"((r)[12]), "=r"((r)[13]), "=r"((r)[14]), "=r"((r)[15]) \
        : "r"(addr))
#endif // TC_OK

#if TC_OK
__global__ void __launch_bounds__(256, 2) __cluster_dims__(2, 2, 1)
#else
__global__ void __launch_bounds__(256, 2)
#endif
lstm_tc(const float* __restrict__ c_in, float* __restrict__ out) {
#if TC_OK
    extern __shared__ char smem[];
    const uint32_t sb = smem_u32(smem);
    const int tid  = threadIdx.x;
    const int wid  = tid >> 5;
    const int lane = tid & 31;
    const int m0   = blockIdx.y * TILE_M;
    const int nblk = blockIdx.x;
    const int c0   = nblk * 64;

    // Cluster roles: ctarank = (x&1) + 2*(y&1)
    const int ni = blockIdx.x & 1;        // rank bit 0
    const int mi = blockIdx.y & 1;        // rank bit 1
    const uint16_t maskA = mi ? 0b1100 : 0b0011;   // same-m pair (shares A)
    const uint16_t maskW = ni ? 0b1010 : 0b0101;   // same-n pair (shares W)

    const uint32_t full_bar0  = sb + 64;   // 2 bars, tx-based, count 1
    const uint32_t empty_bar0 = sb + 96;   // 2 bars, count 4 (quad commits)
    const uint32_t done_bar   = sb + 128;

    if (wid == 0) { TC_ALLOC(sb, 256); TC_RELINQ(); }
    if (tid == 0) {
        for (int s = 0; s < TCS; s++) {
            mbar_init(full_bar0 + s * 8, 1);
            mbar_init(empty_bar0 + s * 8, 4);
        }
        mbar_init(done_bar, 1);
    }
    float* bias_s = reinterpret_cast<float*>(smem + 1024);
    if (tid < 256) bias_s[tid] = g_bias[(tid >> 6) * HIDN + c0 + (tid & 63)];
    __syncthreads();

    // All quad members' mbarriers must be live before any multicast targets them.
    CLUSTER_SYNC();

    uint32_t tmem;
    asm volatile("ld.shared.b32 %0, [%1];" : "=r"(tmem) : "r"(sb));

    if (tid == 0) {
        // Producer: every CTA expects the full stage tx; only role owners copy.
        const char* Abase = reinterpret_cast<const char*>(&g_A[blockIdx.y][0][0]);
        const char* Bbase = reinterpret_cast<const char*>(&g_W[nblk][0][0]);
        for (int ch = 0; ch < N_CHUNKS; ch++) {
            const int s = ch & (TCS - 1);
            if (ch >= TCS) mbar_wait(empty_bar0 + s * 8, ((ch - TCS) / TCS) & 1);
            mbar_expect_tx(full_bar0 + s * 8, STAGE_BYTES);
            uint32_t stA = sb + SMEM_HDR + s * STAGE_BYTES;
            if (ni == 0)   // A owner for the same-m pair
                bulk_g2s_mc(stA, Abase + ch * A_BYTES, A_BYTES,
                            full_bar0 + s * 8, maskA);
            if (mi == 0)   // W owner for the same-n pair
                bulk_g2s_mc(stA + A_BYTES, Bbase + ch * B_BYTES, B_BYTES,
                            full_bar0 + s * 8, maskW);
        }
    } else if (tid == 32) {
        // MMA issuer; stage release is quad-wide via multicast commit.
        for (int ch = 0; ch < N_CHUNKS; ch++) {
            const int s = ch & (TCS - 1);
            mbar_wait(full_bar0 + s * 8, (ch / TCS) & 1);
            uint32_t stA = sb + SMEM_HDR + s * STAGE_BYTES;
            uint64_t ad = make_desc(stA);
            uint64_t bd = make_desc(stA + A_BYTES);
            #pragma unroll
            for (int ks = 0; ks < 4; ks++) {
                mma_f16_ss(tmem, ad + ks * 2, bd + ks * 2, MMA_IDESC,
                           (ch == 0 && ks == 0) ? 0u : 1u);
            }
            TC_COMMIT_MC(empty_bar0 + s * 8, 0xF);
        }
        TC_COMMIT(done_bar);
    }

    mbar_wait(done_bar, 0);
    TC_FENCE_AFTER();

    // Epilogue: 8 warps. Warp w: subpartition sp=w&3 (rows sp*32+lane),
    // column half (w>>2)*32, processed as two 16-col blocks.
    const int sp = wid & 3, half = wid >> 2;
    const int r = sp * 32 + lane;
    const float* crow = c_in + (size_t)(m0 + r) * HIDN + c0;
    float*       hrow = out + (size_t)(m0 + r) * HIDN + c0;
    float*       orow = out + (size_t)B_SZ * HIDN + (size_t)(m0 + r) * HIDN + c0;

    #pragma unroll
    for (int jb = 0; jb < 2; jb++) {
        const int j = half * 32 + jb * 16;
        float cv[16];
        #pragma unroll
        for (int q = 0; q < 4; q++)
            *reinterpret_cast<float4*>(&cv[q * 4]) =
                *reinterpret_cast<const float4*>(crow + j + q * 4);

        uint32_t ri[16], rg[16], rf[16], ro[16];
        TC_LD_X16(ri, tmem + 0 + j);
        TC_LD_X16(rg, tmem + 64 + j);
        TC_LD_X16(rf, tmem + 128 + j);
        TC_LD_X16(ro, tmem + 192 + j);
        TC_WAIT_LD();

        float hn[16], cn[16];
        #pragma unroll
        for (int q = 0; q < 16; q++) {
            const int jj = j + q;
            float iv = fast_sigmoid(__uint_as_float(ri[q]) + bias_s[jj]);
            float gv = tanh_ap(__uint_as_float(rg[q]) + bias_s[64 + jj]);
            float fv = fast_sigmoid(__uint_as_float(rf[q]) + bias_s[128 + jj]);
            float ov = fast_sigmoid(__uint_as_float(ro[q]) + bias_s[192 + jj]);
            float c2 = fv * cv[q] + iv * gv;
            cn[q] = c2;
            hn[q] = ov * tanh_ap(c2);
        }
        #pragma unroll
        for (int q = 0; q < 4; q++) {
            *reinterpret_cast<float4*>(hrow + j + q * 4) =
                *reinterpret_cast<const float4*>(&hn[q * 4]);
            *reinterpret_cast<float4*>(orow + j + q * 4) =
                *reinterpret_cast<const float4*>(&cn[q * 4]);
        }
    }

    __syncthreads();
    if (wid == 0) { TC_DEALLOC(tmem, 256); }
    // No CTA may exit while quad peers might still multicast into its SMEM /
    // commit into its barriers.
    CLUSTER_SYNC();
#endif // TC_OK
}

// ============================================================================
// HMMA fallback path (plain sm_103): mma.sync m16n8k16 f16->f32
// ============================================================================

DINL void ldsm_x4(uint32_t& r0, uint32_t& r1, uint32_t& r2, uint32_t& r3, uint32_t addr) {
    asm volatile("ldmatrix.sync.aligned.m8n8.x4.shared.b16 {%0,%1,%2,%3}, [%4];"
                 : "=r"(r0), "=r"(r1), "=r"(r2), "=r"(r3) : "r"(addr));
}
DINL void mma16816(float* d, uint32_t a0, uint32_t a1, uint32_t a2, uint32_t a3,
                   uint32_t b0, uint32_t b1) {
    asm volatile(
        "mma.sync.aligned.m16n8k16.row.col.f32.f16.f16.f32 "
        "{%0,%1,%2,%3}, {%4,%5,%6,%7}, {%8,%9}, {%0,%1,%2,%3};"
        : "+f"(d[0]), "+f"(d[1]), "+f"(d[2]), "+f"(d[3])
        : "r"(a0), "r"(a1), "r"(a2), "r"(a3), "r"(b0), "r"(b1));
}

constexpr int FB_THREADS = 544;   // 16 compute warps + 1 producer warp

__global__ void __launch_bounds__(FB_THREADS, 1)
lstm_fb(const float* __restrict__ c_in, float* __restrict__ out) {
    extern __shared__ char smem[];
    const uint32_t sb = smem_u32(smem);
    const int tid  = threadIdx.x;
    const int wid  = tid >> 5;
    const int lane = tid & 31;
    const int m0   = blockIdx.y * TILE_M;
    const int nblk = blockIdx.x;
    const int c0   = nblk * 64;

    const uint32_t full_bar0  = sb + 64;   // 4 bars, tx-based
    const uint32_t empty_bar0 = sb + 96;   // 4 bars, arrive count 16

    float* bias_s = reinterpret_cast<float*>(smem + 1024);

    if (tid == 0) {
        for (int s = 0; s < FBS; s++) {
            mbar_init(full_bar0 + s * 8, 1);
            mbar_init(empty_bar0 + s * 8, 16);
        }
    }
    if (tid < 256) bias_s[tid] = g_bias[(tid >> 6) * HIDN + c0 + (tid & 63)];
    __syncthreads();

    const char* Abase = reinterpret_cast<const char*>(&g_A[blockIdx.y][0][0]);
    const char* Bbase = reinterpret_cast<const char*>(&g_W[nblk][0][0]);

    if (wid == 16) {
        if (lane == 0) {
            for (int ch = 0; ch < N_CHUNKS; ch++) {
                const int s = ch & 3;
                if (ch >= FBS) mbar_wait(empty_bar0 + s * 8, ((ch - FBS) >> 2) & 1);
                mbar_expect_tx(full_bar0 + s * 8, STAGE_BYTES);
                uint32_t stA = sb + SMEM_HDR + s * STAGE_BYTES;
                bulk_g2s(stA, Abase + ch * A_BYTES, A_BYTES, full_bar0 + s * 8);
                bulk_g2s(stA + A_BYTES, Bbase + ch * B_BYTES, B_BYTES, full_bar0 + s * 8);
            }
        }
    } else {
        const int warp_m = (wid >> 2) * 32;
        const int warp_n = (wid & 3) * 64;

        int rA[2], xA[2];
        #pragma unroll
        for (int mt = 0; mt < 2; mt++) {
            int r = warp_m + mt * 16 + (lane & 7) + ((lane >> 3) & 1) * 8;
            rA[mt] = r * 128;
            xA[mt] = (r & 7) << 4;
        }
        const int acb = (lane >> 4) * 16;
        int rB[4], xB[4];
        #pragma unroll
        for (int nt = 0; nt < 4; nt++) {
            int r = warp_n + nt * 16 + (lane & 7) + ((lane >> 4) & 1) * 8;
            rB[nt] = r * 128;
            xB[nt] = (r & 7) << 4;
        }
        const int bcb = ((lane >> 3) & 1) * 16;

        float acc[2][8][4];
        #pragma unroll
        for (int i = 0; i < 2; i++)
            #pragma unroll
            for (int j = 0; j < 8; j++)
                #pragma unroll
                for (int k = 0; k < 4; k++) acc[i][j][k] = 0.f;

        for (int ch = 0; ch < N_CHUNKS; ch++) {
            const int s = ch & 3;
            mbar_wait(full_bar0 + s * 8, (ch >> 2) & 1);
            const uint32_t stA = sb + SMEM_HDR + s * STAGE_BYTES;
            const uint32_t stB = stA + A_BYTES;

            #pragma unroll
            for (int ks = 0; ks < 4; ks++) {
                const int kb = ks * 32;
                uint32_t a[2][4];
                #pragma unroll
                for (int mt = 0; mt < 2; mt++)
                    ldsm_x4(a[mt][0], a[mt][1], a[mt][2], a[mt][3],
                            stA + rA[mt] + ((kb + acb) ^ xA[mt]));
                uint32_t b[4][4];
                #pragma unroll
                for (int nt = 0; nt < 4; nt++)
                    ldsm_x4(b[nt][0], b[nt][1], b[nt][2], b[nt][3],
                            stB + rB[nt] + ((kb + bcb) ^ xB[nt]));
                #pragma unroll
                for (int mt = 0; mt < 2; mt++)
                    #pragma unroll
                    for (int nn = 0; nn < 8; nn++) {
                        const int nt = nn >> 1, hi = (nn & 1) * 2;
                        mma16816(acc[mt][nn], a[mt][0], a[mt][1], a[mt][2], a[mt][3],
                                 b[nt][hi], b[nt][hi + 1]);
                    }
            }
            if (lane == 0) mbar_arrive(empty_bar0 + s * 8);
        }

        __syncthreads();
        constexpr int GS = 264;
        float* gs = reinterpret_cast<float*>(smem + SMEM_HDR);
        #pragma unroll
        for (int mt = 0; mt < 2; mt++)
            #pragma unroll
            for (int nn = 0; nn < 8; nn++) {
                const int row = warp_m + mt * 16 + (lane >> 2);
                const int col = warp_n + nn * 8 + (lane & 3) * 2;
                gs[row * GS + col]           = acc[mt][nn][0];
                gs[row * GS + col + 1]       = acc[mt][nn][1];
                gs[(row + 8) * GS + col]     = acc[mt][nn][2];
                gs[(row + 8) * GS + col + 1] = acc[mt][nn][3];
            }
    }

    if (wid == 16) __syncthreads();
    __syncthreads();

    constexpr int GS = 264;
    float* gs = reinterpret_cast<float*>(smem + SMEM_HDR);
    const int hbase = m0 * HIDN + c0;
    for (int v = tid; v < TILE_M * 16; v += FB_THREADS) {
        const int r = v >> 4, j = (v & 15) * 4;
        float4 cv = *reinterpret_cast<const float4*>(&c_in[(m0 + r) * HIDN + c0 + j]);
        float4 hn, cn;
        #pragma unroll
        for (int q = 0; q < 4; q++) {
            const int jj = j + q;
            float iv = fast_sigmoid(gs[r * GS + jj]       + bias_s[jj]);
            float gv = tanh_ap     (gs[r * GS + 64 + jj]  + bias_s[64 + jj]);
            float fv = fast_sigmoid(gs[r * GS + 128 + jj] + bias_s[128 + jj]);
            float ov = fast_sigmoid(gs[r * GS + 192 + jj] + bias_s[192 + jj]);
            float c_old = (q == 0) ? cv.x : (q == 1) ? cv.y : (q == 2) ? cv.z : cv.w;
            float c_new = fv * c_old + iv * gv;
            float h_new = ov * tanh_ap(c_new);
            reinterpret_cast<float*>(&cn)[q] = c_new;
            reinterpret_cast<float*>(&hn)[q] = h_new;
        }
        *reinterpret_cast<float4*>(&out[hbase + r * HIDN + j]) = hn;
        *reinterpret_cast<float4*>(&out[B_SZ * HIDN + hbase + r * HIDN + j]) = cn;
    }
}

// ============================================================================
// Launch
// ============================================================================

extern "C" void kernel_launch(void* const* d_in, const int* in_sizes, int n_in,
                              void* d_out, int out_size) {
    const float* x = (const float*)d_in[0];
    const float* h = (const float*)d_in[1];
    const float* c = (const float*)d_in[2];
    // gate order in packed layout: 0=i, 1=g, 2=f, 3=o
    const float* Wxi = (const float*)d_in[3];  const float* bxi = (const float*)d_in[4];
    const float* Wxo = (const float*)d_in[5];  const float* bxo = (const float*)d_in[6];
    const float* Wxf = (const float*)d_in[7];  const float* bxf = (const float*)d_in[8];
    const float* Wxg = (const float*)d_in[9];  const float* bxg = (const float*)d_in[10];
    const float* Whi = (const float*)d_in[11]; const float* bhi = (const float*)d_in[12];
    const float* Who = (const float*)d_in[13]; const float* bho = (const float*)d_in[14];
    const float* Whf = (const float*)d_in[15]; const float* bhf = (const float*)d_in[16];
    const float* Whg = (const float*)d_in[17]; const float* bhg = (const float*)d_in[18];

    pack_A<<<(B_SZ * KDIM / 4 + 255) / 256, 256>>>(x, h);
    pack_W<<<(4 * HIDN * KDIM / 4 + 255) / 256, 256>>>(Wxi, Wxg, Wxf, Wxo, Whi, Whg, Whf, Who);
    pack_bias<<<8, 256>>>(bxi, bxg, bxf, bxo, bhi, bhg, bhf, bho);

    // Host-side path selection: the tcgen05 kernel only has a real body when
    // the loaded cubin came from a 103a-feature gencode pass.
    cudaFuncAttributes attr;
    cudaFuncGetAttributes(&attr, lstm_tc);
    const bool use_tc = attr.numRegs > 40;

    dim3 grid(8, B_SZ / TILE_M);
    if (use_tc) {
        cudaFuncSetAttribute(lstm_tc, cudaFuncAttributeMaxDynamicSharedMemorySize, SMEM_TOTAL_TC);
        lstm_tc<<<grid, 256, SMEM_TOTAL_TC>>>(c, (float*)d_out);
    } else {
        cudaFuncSetAttribute(lstm_fb, cudaFuncAttributeMaxDynamicSharedMemorySize, SMEM_TOTAL_FB);
        lstm_fb<<<grid, FB_THREADS, SMEM_TOTAL_FB>>>(c, (float*)d_out);
    }
}

// round 11
// speedup vs baseline: 1.0987x; 1.0987x over previous
#include <cuda_runtime.h>
#include <cuda_fp16.h>
#include <cstdint>

// ============================================================================
// LSTMCell: gates = [x|h] @ [Wx|Wh]^T + b, then elementwise LSTM math.
// M=16384, N=2048 (4 gates x 512), K=1024.  fp16 tcgen05 GEMM, fp32 accum.
//
// Live path: tcgen05 (sm_103a gencode), 2 CTAs/SM, NO cluster (R8 showed the
// chip is pipeline-latency-bound, not L2-BW-bound). 4-stage / 24KB pipeline:
// SW64 (64B-row) packed tiles, K_CHUNK=32, 32 chunks, so the producer runs
// 4 chunks ahead and hides TMA + commit latency completely.
// ============================================================================

#define DINL __device__ __forceinline__

#if defined(__CUDA_ARCH__)
# if defined(__CUDA_ARCH_FEAT_SM103_ALL) || defined(__CUDA_ARCH_FEAT_SM100_ALL)
#  define TC_OK 1
# else
#  define TC_OK 0
# endif
#else
# define TC_OK 0
#endif

constexpr int B_SZ   = 16384;
constexpr int HIDN   = 512;
constexpr int KDIM   = 1024;
constexpr int TILE_M = 128;
constexpr int MMA_N  = 256;               // 4 gates * 64 hidden cols
constexpr int K_CHUNK = 32;               // fp16 elems per chunk (64 bytes/row)
constexpr int N_CHUNKS = KDIM / K_CHUNK;  // 32
constexpr int A_BYTES = TILE_M * 64;      // 8192
constexpr int B_BYTES = MMA_N * 64;       // 16384
constexpr int STAGE_BYTES = A_BYTES + B_BYTES; // 24576
constexpr int TCS = 4;                    // 4 stages -> 96KB, 2 CTAs/SM

constexpr int SMEM_HDR = 2048;
constexpr int SMEM_TOTAL_TC = SMEM_HDR + TCS * STAGE_BYTES;   // 100352

// Pre-packed operands (device globals; no runtime allocation).
// g_A[m_tile][k_chunk] : 128x32 fp16 tile, SW64-swizzled 64B rows, 8KB
// g_W[n_blk][k_chunk]  : 256x32 fp16 tile (4 gates x 64 cols), SW64, 16KB
__device__ __align__(1024) __half g_A[B_SZ / TILE_M][N_CHUNKS][TILE_M * K_CHUNK];
__device__ __align__(1024) __half g_W[8][N_CHUNKS][MMA_N * K_CHUNK];
__device__ float g_bias[4 * HIDN];

DINL uint32_t smem_u32(const void* p) {
    uint32_t a;
    asm("{ .reg .u64 t; cvta.to.shared.u64 t, %1; cvt.u32.u64 %0, t; }" : "=r"(a) : "l"(p));
    return a;
}
DINL void mbar_init(uint32_t a, uint32_t cnt) {
    asm volatile("mbarrier.init.shared.b64 [%0], %1;" :: "r"(a), "r"(cnt) : "memory");
}
DINL void mbar_expect_tx(uint32_t a, uint32_t bytes) {
    asm volatile("mbarrier.arrive.expect_tx.shared.b64 _, [%0], %1;" :: "r"(a), "r"(bytes) : "memory");
}
DINL void mbar_wait(uint32_t a, uint32_t parity) {
    asm volatile(
        "{\n\t.reg .pred P;\n\t"
        "W_%=:\n\t"
        "mbarrier.try_wait.parity.acquire.cta.shared::cta.b64 P, [%0], %1, 0x989680;\n\t"
        "@P bra.uni D_%=;\n\t"
        "bra.uni W_%=;\n\t"
        "D_%=:\n\t}"
        :: "r"(a), "r"(parity) : "memory");
}
DINL void bulk_g2s(uint32_t dst, const void* src, uint32_t bytes, uint32_t mbar) {
    asm volatile(
        "cp.async.bulk.shared::cta.global.mbarrier::complete_tx::bytes [%0], [%1], %2, [%3];"
        :: "r"(dst), "l"(src), "r"(bytes), "r"(mbar) : "memory");
}

DINL uint32_t sw64(uint32_t off) { return off ^ ((off >> 3) & 0x30); }
DINL float tanh_ap(float x) {
    float y;
    asm("tanh.approx.f32 %0, %1;" : "=f"(y) : "f"(x));
    return y;
}
DINL float fast_sigmoid(float x) { return __fmaf_rn(tanh_ap(0.5f * x), 0.5f, 0.5f); }

// ============================================================================
// Prep kernels (arch-independent, float4 vectorized, SW64 64B-row layout)
// ============================================================================

__global__ void pack_A(const float* __restrict__ x, const float* __restrict__ h) {
    int idx = blockIdx.x * blockDim.x + threadIdx.x;
    int e = idx * 4;
    if (e >= B_SZ * KDIM) return;
    int m = e >> 10, k = e & 1023;
    const float* src = (k < 512) ? (x + m * 512 + k) : (h + m * 512 + (k - 512));
    float4 v = *reinterpret_cast<const float4*>(src);
    __half2 h0 = __floats2half2_rn(v.x, v.y);
    __half2 h1 = __floats2half2_rn(v.z, v.w);
    uint2 hv;
    hv.x = *reinterpret_cast<uint32_t*>(&h0);
    hv.y = *reinterpret_cast<uint32_t*>(&h1);
    int mt = m >> 7, r = m & 127, kc = k >> 5, cc = k & 31;
    uint32_t off = sw64((uint32_t)(r * 64 + cc * 2));
    *reinterpret_cast<uint2*>(reinterpret_cast<char*>(&g_A[mt][kc][0]) + off) = hv;
}

__global__ void pack_W(const float* __restrict__ Wx0, const float* __restrict__ Wx1,
                       const float* __restrict__ Wx2, const float* __restrict__ Wx3,
                       const float* __restrict__ Wh0, const float* __restrict__ Wh1,
                       const float* __restrict__ Wh2, const float* __restrict__ Wh3) {
    int idx = blockIdx.x * blockDim.x + threadIdx.x;
    int e = idx * 4;
    if (e >= 4 * HIDN * KDIM) return;
    int g = e >> 19;
    int rem = e & ((1 << 19) - 1);
    int j = rem >> 10, k = rem & 1023;
    const float* Wx = (g == 0) ? Wx0 : (g == 1) ? Wx1 : (g == 2) ? Wx2 : Wx3;
    const float* Wh = (g == 0) ? Wh0 : (g == 1) ? Wh1 : (g == 2) ? Wh2 : Wh3;
    const float* src = (k < 512) ? (Wx + j * 512 + k) : (Wh + j * 512 + (k - 512));
    float4 v = *reinterpret_cast<const float4*>(src);
    __half2 h0 = __floats2half2_rn(v.x, v.y);
    __half2 h1 = __floats2half2_rn(v.z, v.w);
    uint2 hv;
    hv.x = *reinterpret_cast<uint32_t*>(&h0);
    hv.y = *reinterpret_cast<uint32_t*>(&h1);
    int nblk = j >> 6;
    int row = g * 64 + (j & 63);
    int kc = k >> 5, cc = k & 31;
    uint32_t off = sw64((uint32_t)(row * 64 + cc * 2));
    *reinterpret_cast<uint2*>(reinterpret_cast<char*>(&g_W[nblk][kc][0]) + off) = hv;
}

__global__ void pack_bias(const float* __restrict__ bx0, const float* __restrict__ bx1,
                          const float* __restrict__ bx2, const float* __restrict__ bx3,
                          const float* __restrict__ bh0, const float* __restrict__ bh1,
                          const float* __restrict__ bh2, const float* __restrict__ bh3) {
    int t = blockIdx.x * blockDim.x + threadIdx.x;
    if (t >= 4 * HIDN) return;
    int g = t >> 9, j = t & 511;
    const float* bx = (g == 0) ? bx0 : (g == 1) ? bx1 : (g == 2) ? bx2 : bx3;
    const float* bh = (g == 0) ? bh0 : (g == 1) ? bh1 : (g == 2) ? bh2 : bh3;
    g_bias[t] = bx[j] + bh[j];
}

// ============================================================================
// tcgen05 path (compiles only on sm_103a/sm_100a PTX targets)
// ============================================================================
#if TC_OK

constexpr uint32_t MMA_IDESC = (8u << 24) | ((MMA_N / 8) << 17) | (1u << 4);
// SW64: layout_type=4, version=1 (Blackwell), SBO=32 (512B = 8 rows x 64B), LBO=1
constexpr uint64_t SMEM_DESC_BASE_SW64 =
    (uint64_t(4) << 61) | (uint64_t(1) << 46) | (uint64_t(32) << 32) | (uint64_t(1) << 16);

DINL uint64_t make_desc(uint32_t smem_addr) {
    return SMEM_DESC_BASE_SW64 | ((uint64_t)(smem_addr >> 4) & 0x3FFF);
}
DINL void mma_f16_ss(uint32_t d, uint64_t a, uint64_t b, uint32_t idesc, uint32_t en) {
    asm volatile(
        "{\n\t.reg .pred p;\n\t"
        "setp.ne.u32 p, %4, 0;\n\t"
        "tcgen05.mma.cta_group::1.kind::f16 [%0], %1, %2, %3, {%5, %5, %5, %5}, p;\n\t}"
        :: "r"(d), "l"(a), "l"(b), "r"(idesc), "r"(en), "r"(0u) : "memory");
}
#define TC_ALLOC(sm, n)   asm volatile("tcgen05.alloc.cta_group::1.sync.aligned.shared::cta.b32 [%0], %1;" :: "r"(sm), "r"(n) : "memory")
#define TC_DEALLOC(t, n)  asm volatile("tcgen05.dealloc.cta_group::1.sync.aligned.b32 %0, %1;" :: "r"(t), "r"(n))
#define TC_RELINQ()       asm volatile("tcgen05.relinquish_alloc_permit.cta_group::1.sync.aligned;")
#define TC_COMMIT(mb)     asm volatile("tcgen05.commit.cta_group::1.mbarrier::arrive::one.shared::cluster.b64 [%0];" :: "r"(mb) : "memory")
#define TC_FENCE_AFTER()  asm volatile("tcgen05.fence::after_thread_sync;" ::: "memory")
#define TC_WAIT_LD()      asm volatile("tcgen05.wait::ld.sync.aligned;" ::: "memory")

#define TC_LD_X16(r, addr) \
    asm volatile( \
        "tcgen05.ld.sync.aligned.32x32b.x16.b32 " \
        "{%0, %1, %2, %3, %4, %5, %6, %7, %8, %9, %10, %11, %12, %13, %14, %15}, [%16];" \
        : "=r"((r)[0]), "=r"((r)[1]), "=r"((r)[2]), "=r"((r)[3]), \
          "=r"((r)[4]), "=r"((r)[5]), "=r"((r)[6]), "=r"((r)[7]), \
          "=r"((r)[8]), "=r"((r)[9]), "=r"((r)[10]), "=r"((r)[11]), \
          "=r"((r)[12]), "=r"((r)[13]), "=r"((r)[14]), "=r"((r)[15]) \
        : "r"(addr))
#endif // TC_OK

__global__ void __launch_bounds__(256, 2)
lstm_tc(const float* __restrict__ c_in, float* __restrict__ out) {
#if TC_OK
    extern __shared__ char smem[];
    const uint32_t sb = smem_u32(smem);
    const int tid  = threadIdx.x;
    const int wid  = tid >> 5;
    const int lane = tid & 31;
    const int m0   = blockIdx.y * TILE_M;
    const int nblk = blockIdx.x;
    const int c0   = nblk * 64;

    const uint32_t full_bar0  = sb + 64;    // 4 bars, tx-based
    const uint32_t empty_bar0 = sb + 128;   // 4 bars, count 1
    const uint32_t done_bar   = sb + 192;

    if (wid == 0) { TC_ALLOC(sb, 256); TC_RELINQ(); }
    if (tid == 0) {
        for (int s = 0; s < TCS; s++) {
            mbar_init(full_bar0 + s * 8, 1);
            mbar_init(empty_bar0 + s * 8, 1);
        }
        mbar_init(done_bar, 1);
    }
    float* bias_s = reinterpret_cast<float*>(smem + 1024);
    if (tid < 256) bias_s[tid] = g_bias[(tid >> 6) * HIDN + c0 + (tid & 63)];
    __syncthreads();

    uint32_t tmem;
    asm volatile("ld.shared.b32 %0, [%1];" : "=r"(tmem) : "r"(sb));

    if (tid == 0) {
        // Producer: linear bulk copies of pre-tiled, pre-swizzled operands.
        const char* Abase = reinterpret_cast<const char*>(&g_A[blockIdx.y][0][0]);
        const char* Bbase = reinterpret_cast<const char*>(&g_W[nblk][0][0]);
        for (int ch = 0; ch < N_CHUNKS; ch++) {
            const int s = ch & (TCS - 1);
            if (ch >= TCS) mbar_wait(empty_bar0 + s * 8, ((ch - TCS) >> 2) & 1);
            mbar_expect_tx(full_bar0 + s * 8, STAGE_BYTES);
            uint32_t stA = sb + SMEM_HDR + s * STAGE_BYTES;
            bulk_g2s(stA, Abase + ch * A_BYTES, A_BYTES, full_bar0 + s * 8);
            bulk_g2s(stA + A_BYTES, Bbase + ch * B_BYTES, B_BYTES, full_bar0 + s * 8);
        }
    } else if (tid == 32) {
        // MMA issuer: 2 K16 steps per chunk (desc +0, +2 within 64B rows).
        for (int ch = 0; ch < N_CHUNKS; ch++) {
            const int s = ch & (TCS - 1);
            mbar_wait(full_bar0 + s * 8, (ch >> 2) & 1);
            uint32_t stA = sb + SMEM_HDR + s * STAGE_BYTES;
            uint64_t ad = make_desc(stA);
            uint64_t bd = make_desc(stA + A_BYTES);
            #pragma unroll
            for (int ks = 0; ks < 2; ks++) {
                mma_f16_ss(tmem, ad + ks * 2, bd + ks * 2, MMA_IDESC,
                           (ch == 0 && ks == 0) ? 0u : 1u);
            }
            TC_COMMIT(empty_bar0 + s * 8);
        }
        TC_COMMIT(done_bar);
    }

    mbar_wait(done_bar, 0);
    TC_FENCE_AFTER();

    // Epilogue: 8 warps. Warp w: subpartition sp=w&3 (rows sp*32+lane),
    // column half (w>>2)*32, processed as two 16-col blocks.
    const int sp = wid & 3, half = wid >> 2;
    const int r = sp * 32 + lane;
    const float* crow = c_in + (size_t)(m0 + r) * HIDN + c0;
    float*       hrow = out + (size_t)(m0 + r) * HIDN + c0;
    float*       orow = out + (size_t)B_SZ * HIDN + (size_t)(m0 + r) * HIDN + c0;

    #pragma unroll
    for (int jb = 0; jb < 2; jb++) {
        const int j = half * 32 + jb * 16;
        float cv[16];
        #pragma unroll
        for (int q = 0; q < 4; q++)
            *reinterpret_cast<float4*>(&cv[q * 4]) =
                *reinterpret_cast<const float4*>(crow + j + q * 4);

        uint32_t ri[16], rg[16], rf[16], ro[16];
        TC_LD_X16(ri, tmem + 0 + j);
        TC_LD_X16(rg, tmem + 64 + j);
        TC_LD_X16(rf, tmem + 128 + j);
        TC_LD_X16(ro, tmem + 192 + j);
        TC_WAIT_LD();

        float hn[16], cn[16];
        #pragma unroll
        for (int q = 0; q < 16; q++) {
            const int jj = j + q;
            float iv = fast_sigmoid(__uint_as_float(ri[q]) + bias_s[jj]);
            float gv = tanh_ap(__uint_as_float(rg[q]) + bias_s[64 + jj]);
            float fv = fast_sigmoid(__uint_as_float(rf[q]) + bias_s[128 + jj]);
            float ov = fast_sigmoid(__uint_as_float(ro[q]) + bias_s[192 + jj]);
            float c2 = fv * cv[q] + iv * gv;
            cn[q] = c2;
            hn[q] = ov * tanh_ap(c2);
        }
        #pragma unroll
        for (int q = 0; q < 4; q++) {
            *reinterpret_cast<float4*>(hrow + j + q * 4) =
                *reinterpret_cast<const float4*>(&hn[q * 4]);
            *reinterpret_cast<float4*>(orow + j + q * 4) =
                *reinterpret_cast<const float4*>(&cn[q * 4]);
        }
    }

    __syncthreads();
    if (wid == 0) { TC_DEALLOC(tmem, 256); }
#endif // TC_OK
}

// ============================================================================
// Fallback (plain sm_103 cubin only; never selected on the 'a' builds the
// bench has loaded every round): simple SIMT GEMM over the packed tiles.
// Correct but slow — exists purely so a non-'a' build still passes.
// ============================================================================

__global__ void lstm_fb(const float* __restrict__ c_in, float* __restrict__ out) {
    // One thread per output element column-group: grid covers B_SZ x 64 per nblk.
    int gidx = blockIdx.x * blockDim.x + threadIdx.x;   // 0 .. B_SZ*HIDN-1
    if (gidx >= B_SZ * HIDN) return;
    int m = gidx >> 9;            // row
    int jcol = gidx & 511;        // hidden col
    int nblk = jcol >> 6, jj = jcol & 63;
    int mt = m >> 7, r = m & 127;

    float acc[4] = {0.f, 0.f, 0.f, 0.f};
    for (int kc = 0; kc < N_CHUNKS; kc++) {
        const __half* At = &g_A[mt][kc][0];
        const __half* Wt = &g_W[nblk][kc][0];
        for (int cc = 0; cc < K_CHUNK; cc++) {
            float av = __half2float(*reinterpret_cast<const __half*>(
                reinterpret_cast<const char*>(At) + sw64((uint32_t)(r * 64 + cc * 2))));
            #pragma unroll
            for (int g = 0; g < 4; g++) {
                int row = g * 64 + jj;
                float wv = __half2float(*reinterpret_cast<const __half*>(
                    reinterpret_cast<const char*>(Wt) + sw64((uint32_t)(row * 64 + cc * 2))));
                acc[g] += av * wv;
            }
        }
    }
    int c0 = nblk * 64;
    float iv = fast_sigmoid(acc[0] + g_bias[c0 + jj]);
    float gv = tanh_ap     (acc[1] + g_bias[512 + c0 + jj]);
    float fv = fast_sigmoid(acc[2] + g_bias[1024 + c0 + jj]);
    float ov = fast_sigmoid(acc[3] + g_bias[1536 + c0 + jj]);
    float cv = c_in[m * HIDN + jcol];
    float cn = fv * cv + iv * gv;
    out[m * HIDN + jcol] = ov * tanh_ap(cn);
    out[B_SZ * HIDN + m * HIDN + jcol] = cn;
}

// ============================================================================
// Launch
// ============================================================================

extern "C" void kernel_launch(void* const* d_in, const int* in_sizes, int n_in,
                              void* d_out, int out_size) {
    const float* x = (const float*)d_in[0];
    const float* h = (const float*)d_in[1];
    const float* c = (const float*)d_in[2];
    // gate order in packed layout: 0=i, 1=g, 2=f, 3=o
    const float* Wxi = (const float*)d_in[3];  const float* bxi = (const float*)d_in[4];
    const float* Wxo = (const float*)d_in[5];  const float* bxo = (const float*)d_in[6];
    const float* Wxf = (const float*)d_in[7];  const float* bxf = (const float*)d_in[8];
    const float* Wxg = (const float*)d_in[9];  const float* bxg = (const float*)d_in[10];
    const float* Whi = (const float*)d_in[11]; const float* bhi = (const float*)d_in[12];
    const float* Who = (const float*)d_in[13]; const float* bho = (const float*)d_in[14];
    const float* Whf = (const float*)d_in[15]; const float* bhf = (const float*)d_in[16];
    const float* Whg = (const float*)d_in[17]; const float* bhg = (const float*)d_in[18];

    pack_A<<<(B_SZ * KDIM / 4 + 255) / 256, 256>>>(x, h);
    pack_W<<<(4 * HIDN * KDIM / 4 + 255) / 256, 256>>>(Wxi, Wxg, Wxf, Wxo, Whi, Whg, Whf, Who);
    pack_bias<<<8, 256>>>(bxi, bxg, bxf, bxo, bhi, bhg, bhf, bho);

    // Host-side path selection: the tcgen05 kernel only has a real body when
    // the loaded cubin came from a 103a-feature gencode pass.
    cudaFuncAttributes attr;
    cudaFuncGetAttributes(&attr, lstm_tc);
    const bool use_tc = attr.numRegs > 40;

    if (use_tc) {
        cudaFuncSetAttribute(lstm_tc, cudaFuncAttributeMaxDynamicSharedMemorySize, SMEM_TOTAL_TC);
        dim3 grid(8, B_SZ / TILE_M);
        lstm_tc<<<grid, 256, SMEM_TOTAL_TC>>>(c, (float*)d_out);
    } else {
        lstm_fb<<<(B_SZ * HIDN + 255) / 256, 256>>>(c, (float*)d_out);
    }
}

// round 12
// speedup vs baseline: 1.1843x; 1.0779x over previous
#include <cuda_runtime.h>
#include <cuda_fp16.h>
#include <cstdint>

// ============================================================================
// LSTMCell: gates = [x|h] @ [Wx|Wh]^T + b, then elementwise LSTM math.
// M=16384, N=2048 (4 gates x 512), K=1024.  fp16 tcgen05 GEMM, fp32 accum.
//
// Live path: tcgen05 (sm_103a gencode). The measured wall is bytes delivered
// into SMEM (L2->NoC->SMEM, ~path-independent). This version reuses each W
// chunk for TWO m-tiles inside one CTA: operand traffic 786 -> 524 MB.
//   CTA = 2 m-tiles x 1 nblk, D0/D1 = 2x256 TMEM cols (full 512), 1 CTA/SM,
//   stage = {A0 8K | A1 8K | W 16K} = 32KB x 4 stages, 512 threads,
//   16-warp epilogue over both m-tiles.
// ============================================================================

#define DINL __device__ __forceinline__

#if defined(__CUDA_ARCH__)
# if defined(__CUDA_ARCH_FEAT_SM103_ALL) || defined(__CUDA_ARCH_FEAT_SM100_ALL)
#  define TC_OK 1
# else
#  define TC_OK 0
# endif
#else
# define TC_OK 0
#endif

constexpr int B_SZ   = 16384;
constexpr int HIDN   = 512;
constexpr int KDIM   = 1024;
constexpr int TILE_M = 128;
constexpr int MMA_N  = 256;               // 4 gates * 64 hidden cols
constexpr int K_CHUNK = 32;               // fp16 elems per chunk (64 bytes/row)
constexpr int N_CHUNKS = KDIM / K_CHUNK;  // 32
constexpr int A_BYTES = TILE_M * 64;      // 8192 per m-tile chunk
constexpr int B_BYTES = MMA_N * 64;       // 16384
constexpr int STAGE_BYTES = 2 * A_BYTES + B_BYTES; // 32768
constexpr int TCS = 4;                    // 4 stages = 128KB

constexpr int SMEM_HDR = 2048;
constexpr int SMEM_TOTAL_TC = SMEM_HDR + TCS * STAGE_BYTES;   // 133120

// Pre-packed operands (device globals; no runtime allocation).
// g_A[m_tile][k_chunk] : 128x32 fp16 tile, SW64-swizzled 64B rows, 8KB
// g_W[n_blk][k_chunk]  : 256x32 fp16 tile (4 gates x 64 cols), SW64, 16KB
__device__ __align__(1024) __half g_A[B_SZ / TILE_M][N_CHUNKS][TILE_M * K_CHUNK];
__device__ __align__(1024) __half g_W[8][N_CHUNKS][MMA_N * K_CHUNK];
__device__ float g_bias[4 * HIDN];

DINL uint32_t smem_u32(const void* p) {
    uint32_t a;
    asm("{ .reg .u64 t; cvta.to.shared.u64 t, %1; cvt.u32.u64 %0, t; }" : "=r"(a) : "l"(p));
    return a;
}
DINL void mbar_init(uint32_t a, uint32_t cnt) {
    asm volatile("mbarrier.init.shared.b64 [%0], %1;" :: "r"(a), "r"(cnt) : "memory");
}
DINL void mbar_expect_tx(uint32_t a, uint32_t bytes) {
    asm volatile("mbarrier.arrive.expect_tx.shared.b64 _, [%0], %1;" :: "r"(a), "r"(bytes) : "memory");
}
DINL void mbar_wait(uint32_t a, uint32_t parity) {
    asm volatile(
        "{\n\t.reg .pred P;\n\t"
        "W_%=:\n\t"
        "mbarrier.try_wait.parity.acquire.cta.shared::cta.b64 P, [%0], %1, 0x989680;\n\t"
        "@P bra.uni D_%=;\n\t"
        "bra.uni W_%=;\n\t"
        "D_%=:\n\t}"
        :: "r"(a), "r"(parity) : "memory");
}
DINL void bulk_g2s(uint32_t dst, const void* src, uint32_t bytes, uint32_t mbar) {
    asm volatile(
        "cp.async.bulk.shared::cta.global.mbarrier::complete_tx::bytes [%0], [%1], %2, [%3];"
        :: "r"(dst), "l"(src), "r"(bytes), "r"(mbar) : "memory");
}

DINL uint32_t sw64(uint32_t off) { return off ^ ((off >> 3) & 0x30); }
DINL float tanh_ap(float x) {
    float y;
    asm("tanh.approx.f32 %0, %1;" : "=f"(y) : "f"(x));
    return y;
}
DINL float fast_sigmoid(float x) { return __fmaf_rn(tanh_ap(0.5f * x), 0.5f, 0.5f); }

// ============================================================================
// Prep kernels (arch-independent, float4 vectorized, SW64 64B-row layout)
// ============================================================================

__global__ void pack_A(const float* __restrict__ x, const float* __restrict__ h) {
    int idx = blockIdx.x * blockDim.x + threadIdx.x;
    int e = idx * 4;
    if (e >= B_SZ * KDIM) return;
    int m = e >> 10, k = e & 1023;
    const float* src = (k < 512) ? (x + m * 512 + k) : (h + m * 512 + (k - 512));
    float4 v = *reinterpret_cast<const float4*>(src);
    __half2 h0 = __floats2half2_rn(v.x, v.y);
    __half2 h1 = __floats2half2_rn(v.z, v.w);
    uint2 hv;
    hv.x = *reinterpret_cast<uint32_t*>(&h0);
    hv.y = *reinterpret_cast<uint32_t*>(&h1);
    int mt = m >> 7, r = m & 127, kc = k >> 5, cc = k & 31;
    uint32_t off = sw64((uint32_t)(r * 64 + cc * 2));
    *reinterpret_cast<uint2*>(reinterpret_cast<char*>(&g_A[mt][kc][0]) + off) = hv;
}

__global__ void pack_W(const float* __restrict__ Wx0, const float* __restrict__ Wx1,
                       const float* __restrict__ Wx2, const float* __restrict__ Wx3,
                       const float* __restrict__ Wh0, const float* __restrict__ Wh1,
                       const float* __restrict__ Wh2, const float* __restrict__ Wh3) {
    int idx = blockIdx.x * blockDim.x + threadIdx.x;
    int e = idx * 4;
    if (e >= 4 * HIDN * KDIM) return;
    int g = e >> 19;
    int rem = e & ((1 << 19) - 1);
    int j = rem >> 10, k = rem & 1023;
    const float* Wx = (g == 0) ? Wx0 : (g == 1) ? Wx1 : (g == 2) ? Wx2 : Wx3;
    const float* Wh = (g == 0) ? Wh0 : (g == 1) ? Wh1 : (g == 2) ? Wh2 : Wh3;
    const float* src = (k < 512) ? (Wx + j * 512 + k) : (Wh + j * 512 + (k - 512));
    float4 v = *reinterpret_cast<const float4*>(src);
    __half2 h0 = __floats2half2_rn(v.x, v.y);
    __half2 h1 = __floats2half2_rn(v.z, v.w);
    uint2 hv;
    hv.x = *reinterpret_cast<uint32_t*>(&h0);
    hv.y = *reinterpret_cast<uint32_t*>(&h1);
    int nblk = j >> 6;
    int row = g * 64 + (j & 63);
    int kc = k >> 5, cc = k & 31;
    uint32_t off = sw64((uint32_t)(row * 64 + cc * 2));
    *reinterpret_cast<uint2*>(reinterpret_cast<char*>(&g_W[nblk][kc][0]) + off) = hv;
}

__global__ void pack_bias(const float* __restrict__ bx0, const float* __restrict__ bx1,
                          const float* __restrict__ bx2, const float* __restrict__ bx3,
                          const float* __restrict__ bh0, const float* __restrict__ bh1,
                          const float* __restrict__ bh2, const float* __restrict__ bh3) {
    int t = blockIdx.x * blockDim.x + threadIdx.x;
    if (t >= 4 * HIDN) return;
    int g = t >> 9, j = t & 511;
    const float* bx = (g == 0) ? bx0 : (g == 1) ? bx1 : (g == 2) ? bx2 : bx3;
    const float* bh = (g == 0) ? bh0 : (g == 1) ? bh1 : (g == 2) ? bh2 : bh3;
    g_bias[t] = bx[j] + bh[j];
}

// ============================================================================
// tcgen05 path (compiles only on sm_103a/sm_100a PTX targets)
// ============================================================================
#if TC_OK

constexpr uint32_t MMA_IDESC = (8u << 24) | ((MMA_N / 8) << 17) | (1u << 4);
// SW64: layout_type=4, version=1 (Blackwell), SBO=32 (512B = 8 rows x 64B), LBO=1
constexpr uint64_t SMEM_DESC_BASE_SW64 =
    (uint64_t(4) << 61) | (uint64_t(1) << 46) | (uint64_t(32) << 32) | (uint64_t(1) << 16);

DINL uint64_t make_desc(uint32_t smem_addr) {
    return SMEM_DESC_BASE_SW64 | ((uint64_t)(smem_addr >> 4) & 0x3FFF);
}
DINL void mma_f16_ss(uint32_t d, uint64_t a, uint64_t b, uint32_t idesc, uint32_t en) {
    asm volatile(
        "{\n\t.reg .pred p;\n\t"
        "setp.ne.u32 p, %4, 0;\n\t"
        "tcgen05.mma.cta_group::1.kind::f16 [%0], %1, %2, %3, {%5, %5, %5, %5}, p;\n\t}"
        :: "r"(d), "l"(a), "l"(b), "r"(idesc), "r"(en), "r"(0u) : "memory");
}
#define TC_ALLOC(sm, n)   asm volatile("tcgen05.alloc.cta_group::1.sync.aligned.shared::cta.b32 [%0], %1;" :: "r"(sm), "r"(n) : "memory")
#define TC_DEALLOC(t, n)  asm volatile("tcgen05.dealloc.cta_group::1.sync.aligned.b32 %0, %1;" :: "r"(t), "r"(n))
#define TC_RELINQ()       asm volatile("tcgen05.relinquish_alloc_permit.cta_group::1.sync.aligned;")
#define TC_COMMIT(mb)     asm volatile("tcgen05.commit.cta_group::1.mbarrier::arrive::one.shared::cluster.b64 [%0];" :: "r"(mb) : "memory")
#define TC_FENCE_AFTER()  asm volatile("tcgen05.fence::after_thread_sync;" ::: "memory")
#define TC_WAIT_LD()      asm volatile("tcgen05.wait::ld.sync.aligned;" ::: "memory")

#define TC_LD_X16(r, addr) \
    asm volatile( \
        "tcgen05.ld.sync.aligned.32x32b.x16.b32 " \
        "{%0, %1, %2, %3, %4, %5, %6, %7, %8, %9, %10, %11, %12, %13, %14, %15}, [%16];" \
        : "=r"((r)[0]), "=r"((r)[1]), "=r"((r)[2]), "=r"((r)[3]), \
          "=r"((r)[4]), "=r"((r)[5]), "=r"((r)[6]), "=r"((r)[7]), \
          "=r"((r)[8]), "=r"((r)[9]), "=r"((r)[10]), "=r"((r)[11]), \
          "=r"((r)[12]), "=r"((r)[13]), "=r"((r)[14]), "=r"((r)[15]) \
        : "r"(addr))
#endif // TC_OK

__global__ void __launch_bounds__(512, 1)
lstm_tc(const float* __restrict__ c_in, float* __restrict__ out) {
#if TC_OK
    extern __shared__ char smem[];
    const uint32_t sb = smem_u32(smem);
    const int tid  = threadIdx.x;
    const int wid  = tid >> 5;
    const int lane = tid & 31;
    const int nblk = blockIdx.x;
    const int c0   = nblk * 64;

    const uint32_t full_bar0  = sb + 64;    // 4 bars, tx-based
    const uint32_t empty_bar0 = sb + 128;   // 4 bars, count 1
    const uint32_t done_bar   = sb + 192;

    if (wid == 0) { TC_ALLOC(sb, 512); TC_RELINQ(); }
    if (tid == 0) {
        for (int s = 0; s < TCS; s++) {
            mbar_init(full_bar0 + s * 8, 1);
            mbar_init(empty_bar0 + s * 8, 1);
        }
        mbar_init(done_bar, 1);
    }
    float* bias_s = reinterpret_cast<float*>(smem + 1024);
    if (tid < 256) bias_s[tid] = g_bias[(tid >> 6) * HIDN + c0 + (tid & 63)];
    __syncthreads();

    uint32_t tmem;
    asm volatile("ld.shared.b32 %0, [%1];" : "=r"(tmem) : "r"(sb));

    if (tid == 0) {
        // Producer: A tiles for both m-tiles + shared W tile per chunk.
        const char* A0base = reinterpret_cast<const char*>(&g_A[blockIdx.y * 2 + 0][0][0]);
        const char* A1base = reinterpret_cast<const char*>(&g_A[blockIdx.y * 2 + 1][0][0]);
        const char* Bbase  = reinterpret_cast<const char*>(&g_W[nblk][0][0]);
        for (int ch = 0; ch < N_CHUNKS; ch++) {
            const int s = ch & (TCS - 1);
            if (ch >= TCS) mbar_wait(empty_bar0 + s * 8, ((ch - TCS) >> 2) & 1);
            mbar_expect_tx(full_bar0 + s * 8, STAGE_BYTES);
            uint32_t st = sb + SMEM_HDR + s * STAGE_BYTES;
            bulk_g2s(st,               A0base + ch * A_BYTES, A_BYTES, full_bar0 + s * 8);
            bulk_g2s(st + A_BYTES,     A1base + ch * A_BYTES, A_BYTES, full_bar0 + s * 8);
            bulk_g2s(st + 2 * A_BYTES, Bbase  + ch * B_BYTES, B_BYTES, full_bar0 + s * 8);
        }
    } else if (tid == 32) {
        // MMA issuer: per chunk, 2 K16 steps x 2 m-tiles sharing the W operand.
        for (int ch = 0; ch < N_CHUNKS; ch++) {
            const int s = ch & (TCS - 1);
            mbar_wait(full_bar0 + s * 8, (ch >> 2) & 1);
            uint32_t st = sb + SMEM_HDR + s * STAGE_BYTES;
            uint64_t ad0 = make_desc(st);
            uint64_t ad1 = make_desc(st + A_BYTES);
            uint64_t bd  = make_desc(st + 2 * A_BYTES);
            const uint32_t en = (ch == 0) ? 0u : 1u;
            mma_f16_ss(tmem,       ad0 + 0, bd + 0, MMA_IDESC, en);
            mma_f16_ss(tmem,       ad0 + 2, bd + 2, MMA_IDESC, 1u);
            mma_f16_ss(tmem + 256, ad1 + 0, bd + 0, MMA_IDESC, en);
            mma_f16_ss(tmem + 256, ad1 + 2, bd + 2, MMA_IDESC, 1u);
            TC_COMMIT(empty_bar0 + s * 8);
        }
        TC_COMMIT(done_bar);
    }

    mbar_wait(done_bar, 0);
    TC_FENCE_AFTER();

    // Epilogue: 16 warps. Warp w: subpartition sp=w&3 (rows sp*32+lane),
    // m-tile mt=(w>>2)&1, column half=(w>>3)&1, two 16-col blocks per half.
    const int sp = wid & 3, mt = (wid >> 2) & 1, half = (wid >> 3) & 1;
    const int r = sp * 32 + lane;
    const int mrow = (blockIdx.y * 2 + mt) * TILE_M + r;
    const uint32_t dbase = tmem + mt * 256;
    const float* crow = c_in + (size_t)mrow * HIDN + c0;
    float*       hrow = out + (size_t)mrow * HIDN + c0;
    float*       orow = out + (size_t)B_SZ * HIDN + (size_t)mrow * HIDN + c0;

    #pragma unroll
    for (int jb = 0; jb < 2; jb++) {
        const int j = half * 32 + jb * 16;
        float cv[16];
        #pragma unroll
        for (int q = 0; q < 4; q++)
            *reinterpret_cast<float4*>(&cv[q * 4]) =
                *reinterpret_cast<const float4*>(crow + j + q * 4);

        uint32_t ri[16], rg[16], rf[16], ro[16];
        TC_LD_X16(ri, dbase + 0 + j);
        TC_LD_X16(rg, dbase + 64 + j);
        TC_LD_X16(rf, dbase + 128 + j);
        TC_LD_X16(ro, dbase + 192 + j);
        TC_WAIT_LD();

        float hn[16], cn[16];
        #pragma unroll
        for (int q = 0; q < 16; q++) {
            const int jj = j + q;
            float iv = fast_sigmoid(__uint_as_float(ri[q]) + bias_s[jj]);
            float gv = tanh_ap(__uint_as_float(rg[q]) + bias_s[64 + jj]);
            float fv = fast_sigmoid(__uint_as_float(rf[q]) + bias_s[128 + jj]);
            float ov = fast_sigmoid(__uint_as_float(ro[q]) + bias_s[192 + jj]);
            float c2 = fv * cv[q] + iv * gv;
            cn[q] = c2;
            hn[q] = ov * tanh_ap(c2);
        }
        #pragma unroll
        for (int q = 0; q < 4; q++) {
            *reinterpret_cast<float4*>(hrow + j + q * 4) =
                *reinterpret_cast<const float4*>(&hn[q * 4]);
            *reinterpret_cast<float4*>(orow + j + q * 4) =
                *reinterpret_cast<const float4*>(&cn[q * 4]);
        }
    }

    __syncthreads();
    if (wid == 0) { TC_DEALLOC(tmem, 512); }
#endif // TC_OK
}

// ============================================================================
// Fallback (plain sm_103 cubin only; never selected on the 'a' builds the
// bench has loaded every round): simple SIMT GEMM over the packed tiles.
// ============================================================================

__global__ void lstm_fb(const float* __restrict__ c_in, float* __restrict__ out) {
    int gidx = blockIdx.x * blockDim.x + threadIdx.x;   // 0 .. B_SZ*HIDN-1
    if (gidx >= B_SZ * HIDN) return;
    int m = gidx >> 9;            // row
    int jcol = gidx & 511;        // hidden col
    int nblk = jcol >> 6, jj = jcol & 63;
    int mt = m >> 7, r = m & 127;

    float acc[4] = {0.f, 0.f, 0.f, 0.f};
    for (int kc = 0; kc < N_CHUNKS; kc++) {
        const __half* At = &g_A[mt][kc][0];
        const __half* Wt = &g_W[nblk][kc][0];
        for (int cc = 0; cc < K_CHUNK; cc++) {
            float av = __half2float(*reinterpret_cast<const __half*>(
                reinterpret_cast<const char*>(At) + sw64((uint32_t)(r * 64 + cc * 2))));
            #pragma unroll
            for (int g = 0; g < 4; g++) {
                int row = g * 64 + jj;
                float wv = __half2float(*reinterpret_cast<const __half*>(
                    reinterpret_cast<const char*>(Wt) + sw64((uint32_t)(row * 64 + cc * 2))));
                acc[g] += av * wv;
            }
        }
    }
    int c0 = nblk * 64;
    float iv = fast_sigmoid(acc[0] + g_bias[c0 + jj]);
    float gv = tanh_ap     (acc[1] + g_bias[512 + c0 + jj]);
    float fv = fast_sigmoid(acc[2] + g_bias[1024 + c0 + jj]);
    float ov = fast_sigmoid(acc[3] + g_bias[1536 + c0 + jj]);
    float cv = c_in[m * HIDN + jcol];
    float cn = fv * cv + iv * gv;
    out[m * HIDN + jcol] = ov * tanh_ap(cn);
    out[B_SZ * HIDN + m * HIDN + jcol] = cn;
}

// ============================================================================
// Launch
// ============================================================================

extern "C" void kernel_launch(void* const* d_in, const int* in_sizes, int n_in,
                              void* d_out, int out_size) {
    const float* x = (const float*)d_in[0];
    const float* h = (const float*)d_in[1];
    const float* c = (const float*)d_in[2];
    // gate order in packed layout: 0=i, 1=g, 2=f, 3=o
    const float* Wxi = (const float*)d_in[3];  const float* bxi = (const float*)d_in[4];
    const float* Wxo = (const float*)d_in[5];  const float* bxo = (const float*)d_in[6];
    const float* Wxf = (const float*)d_in[7];  const float* bxf = (const float*)d_in[8];
    const float* Wxg = (const float*)d_in[9];  const float* bxg = (const float*)d_in[10];
    const float* Whi = (const float*)d_in[11]; const float* bhi = (const float*)d_in[12];
    const float* Who = (const float*)d_in[13]; const float* bho = (const float*)d_in[14];
    const float* Whf = (const float*)d_in[15]; const float* bhf = (const float*)d_in[16];
    const float* Whg = (const float*)d_in[17]; const float* bhg = (const float*)d_in[18];

    pack_A<<<(B_SZ * KDIM / 4 + 255) / 256, 256>>>(x, h);
    pack_W<<<(4 * HIDN * KDIM / 4 + 255) / 256, 256>>>(Wxi, Wxg, Wxf, Wxo, Whi, Whg, Whf, Who);
    pack_bias<<<8, 256>>>(bxi, bxg, bxf, bxo, bhi, bhg, bhf, bho);

    // Host-side path selection: the tcgen05 kernel only has a real body when
    // the loaded cubin came from a 103a-feature gencode pass.
    cudaFuncAttributes attr;
    cudaFuncGetAttributes(&attr, lstm_tc);
    const bool use_tc = attr.numRegs > 40;

    if (use_tc) {
        cudaFuncSetAttribute(lstm_tc, cudaFuncAttributeMaxDynamicSharedMemorySize, SMEM_TOTAL_TC);
        dim3 grid(8, B_SZ / (2 * TILE_M));   // (8 nblks, 64 m-pairs)
        lstm_tc<<<grid, 512, SMEM_TOTAL_TC>>>(c, (float*)d_out);
    } else {
        lstm_fb<<<(B_SZ * HIDN + 255) / 256, 256>>>(c, (float*)d_out);
    }
}